// round 10
// baseline (speedup 1.0000x reference)
#include <cuda_runtime.h>
#include <cuda_fp16.h>
#include <math.h>
#include <stdint.h>

// ---------------- problem constants ----------------
#define BATCHN  16
#define LSEQ    2048
#define INDIM   64
#define HID     256
#define STATE   256
#define MLPD    1024
#define OUTD    128
#define NL      4
#define BL      (BATCHN * LSEQ)      // 32768 rows
#define CL      128                  // scan chunk length
#define NC      (LSEQ / CL)          // 16 chunks

// smem tile layout (bytes): rows padded to 80B — conflict-free ldmatrix
// CTA tile: 128(M) x 64(N), K chunk 32; 3-stage pipeline
#define LDS_ROW   80
#define T_AH      0
#define T_AL      10240              // 128 rows * 80
#define T_BH      20480
#define T_BL      25600              // 64 rows * 80
#define STAGE_B   30720
#define SMEM_BYTES (3 * STAGE_B)     // 92160 -> 2 CTAs/SM (184 KB)

// ---------------- device scratch (static, no allocations) ----------------
__device__ float g_h  [BL * HID];
__device__ float g_y  [BL * HID];
__device__ float g_sre[BL * STATE];
__device__ float g_sim[BL * STATE];
__device__ float g_z  [BL * MLPD];
__device__ float g_cre[BATCHN * NC * STATE];
__device__ float g_cim[BATCHN * NC * STATE];
__device__ float g_ire[BATCHN * NC * STATE];
__device__ float g_iim[BATCHN * NC * STATE];
__device__ float g_lamre[NL * STATE];
__device__ float g_lamim[NL * STATE];
__device__ float g_eg   [NL * STATE];
__device__ float g_negCim[NL * HID * STATE];
__device__ float g_Bpack[NL * 2 * STATE * HID];   // [Bre;Bim] stacked along N

// ---------------- PTX / fp16 helpers ----------------
__device__ __forceinline__ uint32_t smem_u32(const void* p) {
    uint32_t a;
    asm("{ .reg .u64 t; cvta.to.shared.u64 t, %1; cvt.u32.u64 %0, t; }"
        : "=r"(a) : "l"(p));
    return a;
}
// pack two fp32 -> f16x2 (x low, y high), return residuals
__device__ __forceinline__ uint32_t packh_res(float x, float y, float& rx, float& ry) {
    const __half hx = __float2half_rn(x), hy = __float2half_rn(y);
    rx = x - __half2float(hx);
    ry = y - __half2float(hy);
    __half2 p = __halves2half2(hx, hy);
    return *reinterpret_cast<uint32_t*>(&p);
}
__device__ __forceinline__ uint32_t packh(float x, float y) {
    __half2 p = __halves2half2(__float2half_rn(x), __float2half_rn(y));
    return *reinterpret_cast<uint32_t*>(&p);
}
__device__ __forceinline__ void sts64(uint32_t a, uint32_t x, uint32_t y) {
    asm volatile("st.shared.v2.b32 [%0], {%1, %2};" :: "r"(a), "r"(x), "r"(y) : "memory");
}
#define LDSM4(r0, r1, r2, r3, addr) \
    asm volatile("ldmatrix.sync.aligned.m8n8.x4.shared.b16 {%0,%1,%2,%3}, [%4];" \
                 : "=r"(r0), "=r"(r1), "=r"(r2), "=r"(r3) : "r"(addr))
// fp16 inputs, fp32 accumulate (main product)
#define MMA_F32A(d, a, b) \
    asm volatile("mma.sync.aligned.m16n8k16.row.col.f32.f16.f16.f32 " \
                 "{%0,%1,%2,%3},{%4,%5,%6,%7},{%8,%9},{%0,%1,%2,%3};" \
                 : "+f"((d)[0]), "+f"((d)[1]), "+f"((d)[2]), "+f"((d)[3]) \
                 : "r"((a)[0]), "r"((a)[1]), "r"((a)[2]), "r"((a)[3]), \
                   "r"((b)[0]), "r"((b)[1]))
// fp16 inputs, fp16 accumulate (correction products)
#define MMA_F16A(d, a, b) \
    asm volatile("mma.sync.aligned.m16n8k16.row.col.f16.f16.f16.f16 " \
                 "{%0,%1},{%2,%3,%4,%5},{%6,%7},{%0,%1};" \
                 : "+r"((d)[0]), "+r"((d)[1]) \
                 : "r"((a)[0]), "r"((a)[1]), "r"((a)[2]), "r"((a)[3]), \
                   "r"((b)[0]), "r"((b)[1]))

// ---------------- small prep kernels ----------------
__global__ void prep_kernel(const float* __restrict__ nu,
                            const float* __restrict__ th,
                            const float* __restrict__ gl) {
    const int l = blockIdx.x, s = threadIdx.x;
    const int idx = l * STATE + s;
    const float enu = expf(nu[idx]);
    const float eth = expf(th[idx]);
    const float mag = expf(-enu);
    g_lamre[idx] = mag * cosf(eth);
    g_lamim[idx] = mag * sinf(eth);
    g_eg[idx]    = expf(gl[idx]);
}

__global__ void neg_kernel(const float* __restrict__ Cim) {
    const int i = blockIdx.x * 256 + threadIdx.x;
    g_negCim[i] = -Cim[i];
}

// pack [Bre;Bim] along N per layer: rows 0..255=re, 256..511=im
__global__ void pack_kernel(const float* __restrict__ Bre,
                            const float* __restrict__ Bim) {
    const int i = blockIdx.x * 256 + threadIdx.x;       // over NL*STATE*HID
    const int l = i / (STATE * HID);
    const int r = (i / HID) % STATE;
    const int k = i % HID;
    g_Bpack[((size_t)l * 2 * STATE + r) * HID + k]         = Bre[i];
    g_Bpack[((size_t)l * 2 * STATE + STATE + r) * HID + k] = Bim[i];
}

// ---------------- chunked complex diagonal scan ----------------
// pass1: read-only local scan -> chunk carries
__global__ void scan_pass1(int l) {
    const int s = threadIdx.x, c = blockIdx.x, b = blockIdx.y;
    const float lr = g_lamre[l * STATE + s];
    const float li = g_lamim[l * STATE + s];
    size_t idx = ((size_t)(b * LSEQ + c * CL)) * STATE + s;
    float ar = 0.f, ai = 0.f;
    for (int t = 0; t < CL; ++t, idx += STATE) {
        const float br = g_sre[idx], bi = g_sim[idx];
        const float nr = fmaf(lr, ar, fmaf(-li, ai, br));
        const float ni = fmaf(lr, ai, fmaf( li, ar, bi));
        ar = nr; ai = ni;
    }
    const int ci = (b * NC + c) * STATE + s;
    g_cre[ci] = ar; g_cim[ci] = ai;
}

__global__ void scan_pass2(int l, const float* __restrict__ nu,
                           const float* __restrict__ th) {
    const int s = threadIdx.x, b = blockIdx.x;
    const float enu = expf(nu[l * STATE + s]);
    const float eth = expf(th[l * STATE + s]);
    const float r   = expf(-(float)CL * enu);
    const float ang = (float)CL * eth;
    const float Ar = r * cosf(ang), Ai = r * sinf(ang);
    float pr = 0.f, pi = 0.f;
    for (int c = 0; c < NC; ++c) {
        const int ci = (b * NC + c) * STATE + s;
        g_ire[ci] = pr; g_iim[ci] = pi;
        const float cr = g_cre[ci], cii = g_cim[ci];
        const float nr = fmaf(Ar, pr, fmaf(-Ai, pi, cr));
        const float ni = fmaf(Ar, pi, fmaf( Ai, pr, cii));
        pr = nr; pi = ni;
    }
}

// pass3: recurrence seeded with incoming prefix; writes final states
__global__ void scan_pass3(int l) {
    const int s = threadIdx.x, c = blockIdx.x, b = blockIdx.y;
    const int ci = (b * NC + c) * STATE + s;
    const float lr = g_lamre[l * STATE + s];
    const float li = g_lamim[l * STATE + s];
    float ar = g_ire[ci], ai = g_iim[ci];   // zero for c==0
    size_t idx = ((size_t)(b * LSEQ + c * CL)) * STATE + s;
    for (int t = 0; t < CL; ++t, idx += STATE) {
        const float br = g_sre[idx], bi = g_sim[idx];
        const float nr = fmaf(lr, ar, fmaf(-li, ai, br));
        const float ni = fmaf(lr, ai, fmaf( li, ar, bi));
        ar = nr; ai = ni;
        g_sre[idx] = ar; g_sim[idx] = ai;
    }
}

// ---------------- stage store: fp32 float4 -> hi/lo fp16 smem ----------------
__device__ __forceinline__ void store_stage(uint32_t base, const float4* pA,
                                            const float4* pB, int tid)
{
#pragma unroll
    for (int i = 0; i < 4; ++i) {
        const int slot = i * 256 + tid;
        const int r = slot >> 3, c4 = slot & 7;
        const uint32_t off = (uint32_t)(r * LDS_ROW + c4 * 8);
        const float4 f = pA[i];
        float rx, ry, rz, rw;
        const uint32_t h0 = packh_res(f.x, f.y, rx, ry);
        const uint32_t h1 = packh_res(f.z, f.w, rz, rw);
        sts64(base + T_AH + off, h0, h1);
        sts64(base + T_AL + off, packh(rx, ry), packh(rz, rw));
    }
#pragma unroll
    for (int i = 0; i < 2; ++i) {
        const int slot = i * 256 + tid;
        const int r = slot >> 3, c4 = slot & 7;
        const uint32_t off = (uint32_t)(r * LDS_ROW + c4 * 8);
        const float4 f = pB[i];
        float rx, ry, rz, rw;
        const uint32_t h0 = packh_res(f.x, f.y, rx, ry);
        const uint32_t h1 = packh_res(f.z, f.w, rz, rw);
        sts64(base + T_BH + off, h0, h1);
        sts64(base + T_BL + off, packh(rx, ry), packh(rz, rw));
    }
}

// ---------------- fp16-split warp-MMA GEMM: C = A @ W^T + epilogue ----------
// Main product fp32-acc; corrections (al*bh + ah*bl) in fp16-acc, added at end.
// CTA tile 128x64; 8 warps 4(M)x2(N); warp tile 32x32; 3-stage pipeline.
// EPI: 0=+bias 1=gelu(x+bias) 2=+bias+res 3=*scale[col] 4=+scale[col]*res
//      5=*scale[col%STATE], split output halves -> Cout / res(out2)
template <int EPI, bool DUAL>
__global__ void __launch_bounds__(256, 2)
mma_gemm(const float* __restrict__ A,  const float* __restrict__ W,
         const float* __restrict__ A2, const float* __restrict__ W2,
         float* __restrict__ Cout, int N, int K,
         const float* __restrict__ bias, const float* __restrict__ scale,
         const float* __restrict__ res)
{
    extern __shared__ char smem[];
    const uint32_t sb = smem_u32(smem);
    const int tid  = threadIdx.x;
    const int lane = tid & 31, wid = tid >> 5;
    const int wm = wid & 3, wn = wid >> 2;          // warp grid 4(M) x 2(N)
    const int row0 = blockIdx.y * 128, col0 = blockIdx.x * 64;

    float acc[2][4][4];
    uint32_t corr[2][4][2];
#pragma unroll
    for (int mt = 0; mt < 2; ++mt)
#pragma unroll
        for (int nt = 0; nt < 4; ++nt) {
#pragma unroll
            for (int e = 0; e < 4; ++e) acc[mt][nt][e] = 0.f;
            corr[mt][nt][0] = 0u; corr[mt][nt][1] = 0u;
        }

    const int KC   = K >> 5;
    const int CTOT = DUAL ? 2 * KC : KC;

    const uint32_t aOff = (uint32_t)((wm * 32 + (lane & 15)) * LDS_ROW + ((lane >> 4) << 4));
    const uint32_t bOff = (uint32_t)((wn * 32 + (((lane >> 4) << 3) | (lane & 7))) * LDS_ROW
                                     + (((lane >> 3) & 1) << 4));

    float4 pA[4], pB[2];

    auto ldchunk = [&](int c) {
        const int pass = (DUAL && c >= KC) ? 1 : 0;
        const int k0 = (c - (pass ? KC : 0)) << 5;
        const float* Ap = pass ? A2 : A;
        const float* Wp = pass ? W2 : W;
#pragma unroll
        for (int i = 0; i < 4; ++i) {
            const int slot = i * 256 + tid, r = slot >> 3, c4 = slot & 7;
            pA[i] = *(const float4*)(Ap + (size_t)(row0 + r) * K + k0 + c4 * 4);
        }
#pragma unroll
        for (int i = 0; i < 2; ++i) {
            const int slot = i * 256 + tid, r = slot >> 3, c4 = slot & 7;
            pB[i] = *(const float4*)(Wp + (size_t)(col0 + r) * K + k0 + c4 * 4);
        }
    };

    ldchunk(0);
    store_stage(sb, pA, pB, tid);
    if (CTOT > 1) ldchunk(1);
    __syncthreads();

    int bufC = 0, bufS = 1;
    for (int c = 0; c < CTOT; ++c) {
        if (c + 1 < CTOT)
            store_stage(sb + (uint32_t)bufS * STAGE_B, pA, pB, tid);
        if (c + 2 < CTOT) ldchunk(c + 2);

        const uint32_t st = sb + (uint32_t)bufC * STAGE_B;
#pragma unroll
        for (int ks = 0; ks < 2; ++ks) {
            const uint32_t kb = (uint32_t)(ks * 32);
            uint32_t ah[2][4], al[2][4];
#pragma unroll
            for (int mt = 0; mt < 2; ++mt) {
                const uint32_t ad = st + aOff + (uint32_t)(mt * 16 * LDS_ROW) + kb;
                LDSM4(ah[mt][0], ah[mt][1], ah[mt][2], ah[mt][3], ad + T_AH);
                LDSM4(al[mt][0], al[mt][1], al[mt][2], al[mt][3], ad + T_AL);
            }
#pragma unroll
            for (int np = 0; np < 2; ++np) {
                uint32_t bh[2][2], bl[2][2];
                const uint32_t bd = st + bOff + (uint32_t)(np * 16 * LDS_ROW) + kb;
                LDSM4(bh[0][0], bh[0][1], bh[1][0], bh[1][1], bd + T_BH);
                LDSM4(bl[0][0], bl[0][1], bl[1][0], bl[1][1], bd + T_BL);
#pragma unroll
                for (int mt = 0; mt < 2; ++mt)
#pragma unroll
                    for (int j = 0; j < 2; ++j) {
                        const int nt = np * 2 + j;
                        MMA_F32A(acc[mt][nt], ah[mt], bh[j]);
                        MMA_F16A(corr[mt][nt], al[mt], bh[j]);
                        MMA_F16A(corr[mt][nt], ah[mt], bl[j]);
                    }
            }
        }
        __syncthreads();
        bufC = (bufC == 2) ? 0 : bufC + 1;
        bufS = (bufS == 2) ? 0 : bufS + 1;
    }

    // ---- epilogue: add fp16 corrections, apply fused op, write ----
    float* out5 = (EPI == 5 && col0 >= STATE) ? (float*)res : Cout;
    const int cbase5 = (EPI == 5 && col0 >= STATE) ? STATE : 0;

#pragma unroll
    for (int mt = 0; mt < 2; ++mt) {
#pragma unroll
        for (int nt = 0; nt < 4; ++nt) {
            const int rA = row0 + wm * 32 + mt * 16 + (lane >> 2);
            const int cc = col0 + wn * 32 + nt * 8 + (lane & 3) * 2;
#pragma unroll
            for (int half = 0; half < 2; ++half) {
                const int r = rA + half * 8;
                const __half2 ch = *reinterpret_cast<const __half2*>(&corr[mt][nt][half]);
                const float2 cf = __half22float2(ch);
                float v0 = acc[mt][nt][half * 2 + 0] + cf.x;
                float v1 = acc[mt][nt][half * 2 + 1] + cf.y;
                if (EPI == 5) {
                    const int c5 = cc - cbase5;
                    const size_t go5 = (size_t)r * STATE + c5;
                    v0 *= scale[c5]; v1 *= scale[c5 + 1];
                    *(float2*)&out5[go5] = make_float2(v0, v1);
                    continue;
                }
                const size_t go = (size_t)r * N + cc;
                if (EPI == 0) { v0 += bias[cc]; v1 += bias[cc + 1]; }
                if (EPI == 1) {
                    const float t0 = v0 + bias[cc], t1 = v1 + bias[cc + 1];
                    v0 = 0.5f * t0 * (1.0f + erff(t0 * 0.7071067811865476f));
                    v1 = 0.5f * t1 * (1.0f + erff(t1 * 0.7071067811865476f));
                }
                if (EPI == 2) { v0 += bias[cc]     + res[go];
                                v1 += bias[cc + 1] + res[go + 1]; }
                if (EPI == 3) { v0 *= scale[cc]; v1 *= scale[cc + 1]; }
                if (EPI == 4) { v0 = fmaf(scale[cc],     res[go],     v0);
                                v1 = fmaf(scale[cc + 1], res[go + 1], v1); }
                *(float2*)&Cout[go] = make_float2(v0, v1);
            }
        }
    }
}

// ---------------- launch ----------------
extern "C" void kernel_launch(void* const* d_in, const int* in_sizes, int n_in,
                              void* d_out, int out_size)
{
    (void)in_sizes; (void)n_in; (void)out_size;
    const float* x    = (const float*)d_in[0];
    const float* embW = (const float*)d_in[1];
    const float* embB = (const float*)d_in[2];
    const float* nu   = (const float*)d_in[3];
    const float* th   = (const float*)d_in[4];
    const float* gl   = (const float*)d_in[5];
    const float* Bre  = (const float*)d_in[6];
    const float* Bim  = (const float*)d_in[7];
    const float* Cre  = (const float*)d_in[8];
    const float* Cim  = (const float*)d_in[9];
    const float* Dm   = (const float*)d_in[10];
    const float* Wh   = (const float*)d_in[11];
    const float* bh   = (const float*)d_in[12];
    const float* Wo   = (const float*)d_in[13];
    const float* bo   = (const float*)d_in[14];
    const float* outW = (const float*)d_in[15];
    const float* outB = (const float*)d_in[16];
    float* out = (float*)d_out;

    float *h, *y, *sre, *sim, *z, *eg, *negc, *bpack;
    cudaGetSymbolAddress((void**)&h,    g_h);
    cudaGetSymbolAddress((void**)&y,    g_y);
    cudaGetSymbolAddress((void**)&sre,  g_sre);
    cudaGetSymbolAddress((void**)&sim,  g_sim);
    cudaGetSymbolAddress((void**)&z,    g_z);
    cudaGetSymbolAddress((void**)&eg,   g_eg);
    cudaGetSymbolAddress((void**)&negc, g_negCim);
    cudaGetSymbolAddress((void**)&bpack, g_Bpack);

    cudaFuncSetAttribute(mma_gemm<0, false>, cudaFuncAttributeMaxDynamicSharedMemorySize, SMEM_BYTES);
    cudaFuncSetAttribute(mma_gemm<1, false>, cudaFuncAttributeMaxDynamicSharedMemorySize, SMEM_BYTES);
    cudaFuncSetAttribute(mma_gemm<2, false>, cudaFuncAttributeMaxDynamicSharedMemorySize, SMEM_BYTES);
    cudaFuncSetAttribute(mma_gemm<4, true >, cudaFuncAttributeMaxDynamicSharedMemorySize, SMEM_BYTES);
    cudaFuncSetAttribute(mma_gemm<5, false>, cudaFuncAttributeMaxDynamicSharedMemorySize, SMEM_BYTES);

    prep_kernel<<<NL, STATE>>>(nu, th, gl);
    neg_kernel<<<(NL * HID * STATE) / 256, 256>>>(Cim);
    pack_kernel<<<(NL * STATE * HID) / 256, 256>>>(Bre, Bim);

    const dim3 blk(256);

    // embedding: h = x @ embW^T + embB          (BL x 256, K=64)
    mma_gemm<0, false><<<dim3(HID / 64, BL / 128), blk, SMEM_BYTES>>>(
        x, embW, nullptr, nullptr, h, HID, INDIM, embB, nullptr, nullptr);

    for (int l = 0; l < NL; ++l) {
        // Bu(re|im) fused: (h @ [Bre;Bim]^T) * eg[col%256] -> sre / sim
        mma_gemm<5, false><<<dim3((2 * STATE) / 64, BL / 128), blk, SMEM_BYTES>>>(
            h, bpack + (size_t)l * 2 * STATE * HID, nullptr, nullptr, sre,
            2 * STATE, HID, nullptr, eg + l * STATE, sim);

        // diagonal complex scan
        scan_pass1<<<dim3(NC, BATCHN), STATE>>>(l);
        scan_pass2<<<BATCHN, STATE>>>(l, nu, th);
        scan_pass3<<<dim3(NC, BATCHN), STATE>>>(l);

        // y = sre@Cre^T + sim@(-Cim)^T + D[col]*h
        mma_gemm<4, true><<<dim3(HID / 64, BL / 128), blk, SMEM_BYTES>>>(
            sre, Cre + (size_t)l * HID * STATE,
            sim, negc + (size_t)l * HID * STATE, y,
            HID, STATE, nullptr, Dm + l * HID, h);

        // z = gelu(y @ Wh^T + bh)               (BL x 1024, K=256)
        mma_gemm<1, false><<<dim3(MLPD / 64, BL / 128), blk, SMEM_BYTES>>>(
            y, Wh + (size_t)l * MLPD * STATE, nullptr, nullptr, z,
            MLPD, STATE, bh + l * MLPD, nullptr, nullptr);

        // h = z @ Wo^T + bo + y                 (BL x 256, K=1024)
        mma_gemm<2, false><<<dim3(HID / 64, BL / 128), blk, SMEM_BYTES>>>(
            z, Wo + (size_t)l * HID * MLPD, nullptr, nullptr, h,
            HID, MLPD, bo + l * HID, nullptr, y);
    }

    // out = h @ outW^T + outB                   (BL x 128, K=256)
    mma_gemm<0, false><<<dim3(OUTD / 64, BL / 128), blk, SMEM_BYTES>>>(
        h, outW, nullptr, nullptr, out, OUTD, HID, outB, nullptr, nullptr);
}